// round 12
// baseline (speedup 1.0000x reference)
#include <cuda_runtime.h>
#include <cstdint>

#define BB 32
#define NN 1024
#define WW 64
#define RR 4
#define EPSF 1e-5f

// ------------------- device scratch (no allocations allowed) ----------------
__device__ float g_wc[BB*NN];
__device__ float g_alloc[BB*NN];
__device__ float g_ww[BB*NN];
__device__ float g_mem_new[BB*NN*WW];
__device__ __align__(16) float2 g_uv[BB*NN*RR];   // (u, u*w) per (b,m,r)
__device__ float g_scal[BB*8];                    // c[0..3], d[0..3]
__device__ float g_fwd[BB*RR*NN];
__device__ float g_bwdP[64*BB*RR*NN];             // 64 slabs (16 strips x 4 quarters)
__device__ float g_rc[BB*RR*NN];
__device__ float g_rw[BB*RR*NN];
__device__ float g_outP[8*BB*RR*WW];

// ------------------- helpers ------------------------------------------------
__device__ __forceinline__ unsigned long long pack2(float x, float y){
    unsigned long long r; asm("mov.b64 %0, {%1, %2};" : "=l"(r) : "f"(x), "f"(y)); return r;
}
__device__ __forceinline__ void unpack2(unsigned long long p, float &x, float &y){
    asm("mov.b64 {%0, %1}, %2;" : "=f"(x), "=f"(y) : "l"(p));
}
__device__ __forceinline__ void fma2(unsigned long long &d, unsigned long long a, unsigned long long b){
    asm("fma.rn.f32x2 %0, %1, %2, %0;" : "+l"(d) : "l"(a), "l"(b));
}
__device__ __forceinline__ float softplusf(float x){
    return fmaxf(x, 0.0f) + log1pf(expf(-fabsf(x)));
}
__device__ __forceinline__ uint32_t smem_u32(const void* p){
    uint32_t a;
    asm("{ .reg .u64 tmp; cvta.to.shared.u64 tmp, %1; cvt.u32.u64 %0, tmp; }"
        : "=r"(a) : "l"(p));
    return a;
}
__device__ __forceinline__ void cp_async16(uint32_t dst, const void* src){
    asm volatile("cp.async.ca.shared.global [%0], [%1], 16;" :: "r"(dst), "l"(src) : "memory");
}
__device__ __forceinline__ void cp_commit(){
    asm volatile("cp.async.commit_group;" ::: "memory");
}

// ------------------- kernel 1a: write-key dots (sharp) -----------------------
__global__ void __launch_bounds__(128) k_wdot(const float* __restrict__ memory,
                                              const float* __restrict__ wkeys,
                                              const float* __restrict__ wstr) {
    __shared__ float s_key[WW];
    __shared__ float s_kn, s_sp;
    int b = blockIdx.x >> 3;
    int n0 = (blockIdx.x & 7) * 128;
    int t = threadIdx.x;
    if (t < WW) s_key[t] = wkeys[b*WW + t];
    __syncthreads();
    if (t == 0) {
        float ss = 0.f;
        #pragma unroll
        for (int c = 0; c < WW; c++) ss += s_key[c]*s_key[c];
        s_kn = sqrtf(ss + EPSF);
        s_sp = softplusf(wstr[b]);
    }
    __syncthreads();
    int n = n0 + t;
    const float4* row = (const float4*)(memory + ((size_t)(b*NN + n))*WW);
    float dot = 0.f, sq = 0.f;
    #pragma unroll
    for (int j = 0; j < 16; j++) {
        float4 v = row[j];
        dot += v.x*s_key[4*j] + v.y*s_key[4*j+1] + v.z*s_key[4*j+2] + v.w*s_key[4*j+3];
        sq  += v.x*v.x + v.y*v.y + v.z*v.z + v.w*v.w;
    }
    float mn = sqrtf(sq + EPSF);
    g_wc[b*NN + n] = dot / (s_kn*mn + EPSF) * s_sp;
}

// ------------------- kernel 1b: usage + sort + scan -> g_alloc ---------------
__global__ void __launch_bounds__(1024) k_sort(const float* __restrict__ up,
                                               const float* __restrict__ wwp,
                                               const float* __restrict__ fg,
                                               const float* __restrict__ rwp) {
    __shared__ unsigned long long s_sk[NN];
    __shared__ float s_wp[32];
    int b = blockIdx.x, i = threadIdx.x;
    int lane = i & 31, wid = i >> 5;

    float u0 = up[b*NN + i];
    float w0 = wwp[b*NN + i];
    float usage = u0 + (1.f - u0)*w0;
    float phi = 1.f;
    #pragma unroll
    for (int r = 0; r < RR; r++)
        phi *= (1.f - fg[b*RR + r]*rwp[(b*RR + r)*NN + i]);
    usage *= phi;
    float nu = 1.f - usage;

    unsigned long long key =
        ((unsigned long long)__float_as_uint(nu) << 10) | (unsigned int)(NN - 1 - i);
    #pragma unroll
    for (int k = 2; k <= 32; k <<= 1) {
        bool up_ = ((i & k) == 0);
        #pragma unroll
        for (int j = k >> 1; j >= 1; j >>= 1) {
            unsigned long long other = __shfl_xor_sync(~0u, key, j);
            bool lower = ((i & j) == 0);
            bool keepMax = (up_ == lower);
            key = keepMax ? (key > other ? key : other) : (key < other ? key : other);
        }
    }
    s_sk[i] = key;
    __syncthreads();
    for (int k = 64; k <= NN; k <<= 1) {
        for (int j = k >> 1; j >= 32; j >>= 1) {
            int ixj = i ^ j;
            if (ixj > i) {
                unsigned long long a = s_sk[i], c = s_sk[ixj];
                bool desc = ((i & k) == 0);
                if (desc ? (a < c) : (a > c)) { s_sk[i] = c; s_sk[ixj] = a; }
            }
            __syncthreads();
        }
        key = s_sk[i];
        bool up_ = ((i & k) == 0);
        #pragma unroll
        for (int j = 16; j >= 1; j >>= 1) {
            unsigned long long other = __shfl_xor_sync(~0u, key, j);
            bool lower = ((i & j) == 0);
            bool keepMax = (up_ == lower);
            key = keepMax ? (key > other ? key : other) : (key < other ? key : other);
        }
        s_sk[i] = key;
        __syncthreads();
    }

    float snu = __uint_as_float((unsigned int)(key >> 10));
    int oidx = (NN - 1) - (int)(key & (NN - 1));
    float v = 1.f - snu;

    float p = v;
    #pragma unroll
    for (int off = 1; off < 32; off <<= 1) {
        float t2 = __shfl_up_sync(~0u, p, off);
        if (lane >= off) p *= t2;
    }
    if (lane == 31) s_wp[wid] = p;
    __syncthreads();
    if (wid == 0) {
        float q = s_wp[lane];
        #pragma unroll
        for (int off = 1; off < 32; off <<= 1) {
            float t2 = __shfl_up_sync(~0u, q, off);
            if (lane >= off) q *= t2;
        }
        s_wp[lane] = q;
    }
    __syncthreads();
    float warpPref = (wid == 0) ? 1.f : s_wp[wid - 1];
    float inclPrev = __shfl_up_sync(~0u, p, 1);
    float excl = (lane == 0) ? warpPref : warpPref * inclPrev;
    g_alloc[b*NN + oidx] = snu * excl;
}

// ------------------- kernel 2: softmax(wc) + ww + uv + scalars --------------
__global__ void __launch_bounds__(1024) k_alloc2(const float* __restrict__ rwp,
                                                 const float* __restrict__ p_prev,
                                                 const float* __restrict__ ag_,
                                                 const float* __restrict__ wg_) {
    __shared__ float s_red[33];
    __shared__ float s_red8[32][8];
    int b = blockIdx.x, i = threadIdx.x;
    int lane = i & 31, wid = i >> 5;

    float sharp = g_wc[b*NN + i];
    float m = sharp;
    for (int off = 16; off; off >>= 1) m = fmaxf(m, __shfl_xor_sync(~0u, m, off));
    if (lane == 0) s_red[wid] = m;
    __syncthreads();
    if (wid == 0) {
        float mm = s_red[lane];
        for (int off = 16; off; off >>= 1) mm = fmaxf(mm, __shfl_xor_sync(~0u, mm, off));
        if (lane == 0) s_red[32] = mm;
    }
    __syncthreads();
    float e = expf(sharp - s_red[32]);
    float s = e;
    for (int off = 16; off; off >>= 1) s += __shfl_xor_sync(~0u, s, off);
    __syncthreads();
    if (lane == 0) s_red[wid] = s;
    __syncthreads();
    if (wid == 0) {
        float ss = s_red[lane];
        for (int off = 16; off; off >>= 1) ss += __shfl_xor_sync(~0u, ss, off);
        if (lane == 0) s_red[32] = ss;
    }
    __syncthreads();
    float wc = e / s_red[32];

    float alloc = g_alloc[b*NN + i];
    float ag = ag_[b], wg = wg_[b];
    float ww = wg * (ag*alloc + (1.f - ag)*wc);
    g_ww[b*NN + i] = ww;

    float pp = p_prev[b*NN + i];
    float part[8];
    #pragma unroll
    for (int r = 0; r < RR; r++) {
        float u = rwp[(b*RR + r)*NN + i];
        g_uv[(b*NN + i)*RR + r] = make_float2(u, u*ww);
        part[r]     = u*pp;
        part[4 + r] = u*ww;
    }
    #pragma unroll
    for (int j = 0; j < 8; j++)
        for (int off = 16; off; off >>= 1) part[j] += __shfl_xor_sync(~0u, part[j], off);
    if (lane == 0)
        for (int j = 0; j < 8; j++) s_red8[wid][j] = part[j];
    __syncthreads();
    if (wid == 0 && lane < 8) {
        float sum = 0.f;
        #pragma unroll
        for (int w = 0; w < 32; w++) sum += s_red8[w][lane];
        g_scal[b*8 + lane] = sum;
    }
}

// ------------------- kernel 3: fused memory update + read-key dots ----------
__global__ void __launch_bounds__(256) k_memnew_rcdot(const float* __restrict__ memory,
                                                      const float* __restrict__ erase,
                                                      const float* __restrict__ wv,
                                                      const float* __restrict__ rkeys,
                                                      const float* __restrict__ rstr) {
    __shared__ float s_m[128*65];
    __shared__ float s_keys[RR][WW];
    __shared__ float s_kn[RR], s_sp[RR];
    __shared__ float s_e[WW], s_v[WW];
    __shared__ float s_ww[128];
    int b  = blockIdx.x >> 3;
    int n0 = (blockIdx.x & 7) * 128;
    int t  = threadIdx.x;

    if (t < 256) s_keys[t >> 6][t & 63] = rkeys[b*RR*WW + t];
    if (t < WW) { s_e[t] = erase[b*WW + t]; s_v[t] = wv[b*WW + t]; }
    if (t < 128) s_ww[t] = g_ww[b*NN + n0 + t];
    __syncthreads();
    if (t < RR) {
        float ss = 0.f;
        #pragma unroll
        for (int c = 0; c < WW; c++) ss += s_keys[t][c]*s_keys[t][c];
        s_kn[t] = sqrtf(ss + EPSF);
        s_sp[t] = softplusf(rstr[b*RR + t]);
    }

    #pragma unroll
    for (int it = 0; it < 8; it++) {
        int q = it*256 + t;
        int row = q >> 4, c4 = q & 15;
        size_t gi = (size_t)(b*NN + n0 + row)*16 + c4;
        float4 mm = ((const float4*)memory)[gi];
        float ww = s_ww[row];
        float4 o;
        o.x = mm.x*(1.f - ww*s_e[4*c4+0]) + ww*s_v[4*c4+0];
        o.y = mm.y*(1.f - ww*s_e[4*c4+1]) + ww*s_v[4*c4+1];
        o.z = mm.z*(1.f - ww*s_e[4*c4+2]) + ww*s_v[4*c4+2];
        o.w = mm.w*(1.f - ww*s_e[4*c4+3]) + ww*s_v[4*c4+3];
        ((float4*)g_mem_new)[gi] = o;
        float* d = s_m + row*65 + c4*4;
        d[0] = o.x; d[1] = o.y; d[2] = o.z; d[3] = o.w;
    }
    __syncthreads();

    if (t < 128) {
        const float* rw = s_m + t*65;
        float acc0 = 0.f, acc1 = 0.f, acc2 = 0.f, acc3 = 0.f, sq = 0.f;
        #pragma unroll 8
        for (int c = 0; c < WW; c++) {
            float mv = rw[c];
            sq   += mv*mv;
            acc0 += mv*s_keys[0][c];
            acc1 += mv*s_keys[1][c];
            acc2 += mv*s_keys[2][c];
            acc3 += mv*s_keys[3][c];
        }
        float mn = sqrtf(sq + EPSF);
        int n = n0 + t;
        g_rc[(b*RR + 0)*NN + n] = acc0 / (s_kn[0]*mn + EPSF) * s_sp[0];
        g_rc[(b*RR + 1)*NN + n] = acc1 / (s_kn[1]*mn + EPSF) * s_sp[1];
        g_rc[(b*RR + 2)*NN + n] = acc2 / (s_kn[2]*mn + EPSF) * s_sp[2];
        g_rc[(b*RR + 3)*NN + n] = acc3 / (s_kn[3]*mn + EPSF) * s_sp[3];
    }
}

// ------------------- kernel 4: link contraction v6 (cp.async pipeline) ------
// grid = B*16 (b, rb = 64-row strip), 256 threads, 4 CTAs/SM.
// 16 subtiles of 64x64, double-buffered via cp.async.
// fwd: warps 0-3, warp owns 16-col slice, lane owns rows {lane, lane+32}.
// bwd: warps 4-7 = 16-row quarters; lane owns 2 adjacent cols. 64 slabs.
__global__ void __launch_bounds__(256, 4) k_link(const float* __restrict__ L) {
    __shared__ float  s_L[2][64*68];       // 2 x 17408 B (buf0 reused for combine)
    __shared__ float2 s_uvc[2][64*4];      // 2 x 2048 B
    __shared__ float2 s_uvr[64*4];         // 2048 B
    int b  = blockIdx.x >> 4;
    int rb = blockIdx.x & 15;
    int n0 = rb * 64;
    int t  = threadIdx.x;
    int lane = t & 31, wid = t >> 5;

    if (t < 128) ((float4*)s_uvr)[t] = ((const float4*)g_uv)[(size_t)(b*NN + n0)*2 + t];

    uint32_t aL[2]   = { smem_u32(&s_L[0][0]),   smem_u32(&s_L[1][0]) };
    uint32_t aUV[2]  = { smem_u32(&s_uvc[0][0]), smem_u32(&s_uvc[1][0]) };
    const float* Lrow0 = L + (size_t)(b*NN + n0)*NN;
    int prow = t >> 4, pseg = t & 15;      // this thread's 4 tile rows: prow, prow+16, ...

    // prefetch subtile 0
    {
        #pragma unroll
        for (int k = 0; k < 4; k++) {
            int row = prow + k*16;
            cp_async16(aL[0] + (row*68 + pseg*4)*4, Lrow0 + (size_t)row*NN + pseg*4);
        }
        if (t < 128)
            cp_async16(aUV[0] + t*16, (const char*)g_uv + ((size_t)(b*NN)*4 + t*2)*8);
        cp_commit();
    }

    unsigned long long f0[RR] = {0ull,0ull,0ull,0ull};
    unsigned long long f1[RR] = {0ull,0ull,0ull,0ull};
    int wq = wid - 4;                      // bwd warp 0..3 (row quarter)
    int c0 = 2*lane;                       // bwd local cols {c0, c0+1}

    for (int s = 0; s < 16; s++) {
        int buf = s & 1;
        if (s < 15) {
            int nb = buf ^ 1;
            #pragma unroll
            for (int k = 0; k < 4; k++) {
                int row = prow + k*16;
                cp_async16(aL[nb] + (row*68 + pseg*4)*4,
                           Lrow0 + (size_t)row*NN + (s+1)*64 + pseg*4);
            }
            if (t < 128)
                cp_async16(aUV[nb] + t*16,
                           (const char*)g_uv + ((size_t)(b*NN + (s+1)*64)*4 + t*2)*8);
            cp_commit();
            asm volatile("cp.async.wait_group 1;" ::: "memory");
        } else {
            asm volatile("cp.async.wait_group 0;" ::: "memory");
        }
        __syncthreads();

        const float* tile = s_L[buf];
        if (t < 128) {
            const ulonglong2* uvc2 = (const ulonglong2*)s_uvc[buf];
            int qb = wid * 16;
            #pragma unroll
            for (int j = 0; j < 4; j++) {
                float4 a0 = *(const float4*)(tile + lane*68 + qb + 4*j);
                float4 a1 = *(const float4*)(tile + (lane+32)*68 + qb + 4*j);
                #pragma unroll
                for (int jj = 0; jj < 4; jj++) {
                    int m = qb + 4*j + jj;
                    ulonglong2 pA = uvc2[2*m];
                    ulonglong2 pB = uvc2[2*m+1];
                    float x0 = (jj==0)?a0.x:(jj==1)?a0.y:(jj==2)?a0.z:a0.w;
                    float x1 = (jj==0)?a1.x:(jj==1)?a1.y:(jj==2)?a1.z:a1.w;
                    unsigned long long L0 = pack2(x0,x0), L1 = pack2(x1,x1);
                    fma2(f0[0], L0, pA.x); fma2(f0[1], L0, pA.y);
                    fma2(f0[2], L0, pB.x); fma2(f0[3], L0, pB.y);
                    fma2(f1[0], L1, pA.x); fma2(f1[1], L1, pA.y);
                    fma2(f1[2], L1, pB.x); fma2(f1[3], L1, pB.y);
                }
            }
        } else {
            const ulonglong2* uvr2 = (const ulonglong2*)s_uvr;
            unsigned long long ba[RR] = {0ull,0ull,0ull,0ull};
            unsigned long long bb[RR] = {0ull,0ull,0ull,0ull};
            int m0 = wq*16;
            #pragma unroll 4
            for (int mm = 0; mm < 16; mm++) {
                int m = m0 + mm;
                float2 Lv = *(const float2*)(tile + m*68 + c0);
                ulonglong2 pA = uvr2[2*m];
                ulonglong2 pB = uvr2[2*m+1];
                unsigned long long Lx = pack2(Lv.x, Lv.x), Ly = pack2(Lv.y, Lv.y);
                fma2(ba[0], Lx, pA.x); fma2(ba[1], Lx, pA.y);
                fma2(ba[2], Lx, pB.x); fma2(ba[3], Lx, pB.y);
                fma2(bb[0], Ly, pA.x); fma2(bb[1], Ly, pA.y);
                fma2(bb[2], Ly, pB.x); fma2(bb[3], Ly, pB.y);
            }
            int gcol = s*64 + c0;
            float2 w2 = *(const float2*)(g_ww + b*NN + gcol);
            int slab = rb*4 + wq;
            size_t base = (size_t)slab*(BB*RR*NN) + (size_t)(b*RR)*NN + gcol;
            #pragma unroll
            for (int r = 0; r < RR; r++) {
                float A0, B0, A1, B1;
                unpack2(ba[r], A0, B0);
                unpack2(bb[r], A1, B1);
                float2 outv;
                outv.x = (1.f - w2.x)*A0 - B0;
                outv.y = (1.f - w2.y)*A1 - B1;
                *(float2*)(g_bwdP + base + (size_t)r*NN) = outv;
            }
        }
        __syncthreads();
    }

    // fwd cross-warp combine (reuse buf0)
    if (t < 128) {
        float* comb = s_L[0];
        int w4 = wid;
        #pragma unroll
        for (int r = 0; r < RR; r++) {
            float A, Bv;
            unpack2(f0[r], A, Bv);
            comb[lane*32 + w4*8 + 2*r]     = A;
            comb[lane*32 + w4*8 + 2*r + 1] = Bv;
            unpack2(f1[r], A, Bv);
            comb[(lane+32)*32 + w4*8 + 2*r]     = A;
            comb[(lane+32)*32 + w4*8 + 2*r + 1] = Bv;
        }
    }
    __syncthreads();
    {
        const float* comb = s_L[0];
        int row = t >> 2, r = t & 3;
        float A = 0.f, Bv = 0.f;
        #pragma unroll
        for (int w4 = 0; w4 < 4; w4++) {
            A  += comb[row*32 + w4*8 + 2*r];
            Bv += comb[row*32 + w4*8 + 2*r + 1];
        }
        int n = n0 + row;
        float wn = g_ww[b*NN + n];
        g_fwd[(size_t)(b*RR + r)*NN + n] = (1.f - wn)*A - Bv + wn*g_scal[b*8 + r];
    }
}

// ------------------- kernel 5: read softmax + read weights ------------------
__global__ void __launch_bounds__(1024) k_rw(const float* __restrict__ p_prev,
                                             const float* __restrict__ rmode) {
    __shared__ float s_red[33];
    int br = blockIdx.x;
    int b = br >> 2, r = br & 3;
    int t = threadIdx.x, lane = t & 31, wid = t >> 5;

    const float* rm = rmode + br*3;
    float v0 = rm[0], v1 = rm[1], v2 = rm[2];
    float mx3 = fmaxf(v0, fmaxf(v1, v2));
    float e0 = expf(v0 - mx3), e1 = expf(v1 - mx3), e2 = expf(v2 - mx3);
    float inv3 = 1.f / (e0 + e1 + e2);
    float bm = e0*inv3, fm = e1*inv3, cm = e2*inv3;

    float sharp = g_rc[br*NN + t];
    float m = sharp;
    for (int off = 16; off; off >>= 1) m = fmaxf(m, __shfl_xor_sync(~0u, m, off));
    if (lane == 0) s_red[wid] = m;
    __syncthreads();
    if (wid == 0) {
        float mm = s_red[lane];
        for (int off = 16; off; off >>= 1) mm = fmaxf(mm, __shfl_xor_sync(~0u, mm, off));
        if (lane == 0) s_red[32] = mm;
    }
    __syncthreads();
    float e = expf(sharp - s_red[32]);
    float s = e;
    for (int off = 16; off; off >>= 1) s += __shfl_xor_sync(~0u, s, off);
    __syncthreads();
    if (lane == 0) s_red[wid] = s;
    __syncthreads();
    if (wid == 0) {
        float ss = s_red[lane];
        for (int off = 16; off; off >>= 1) ss += __shfl_xor_sync(~0u, ss, off);
        if (lane == 0) s_red[32] = ss;
    }
    __syncthreads();
    float rc = e / s_red[32];

    float bsum = 0.f;
    #pragma unroll
    for (int sl = 0; sl < 64; sl++)
        bsum += g_bwdP[(size_t)sl*(BB*RR*NN) + (size_t)br*NN + t];
    float bwd = bsum + p_prev[b*NN + t]*g_scal[b*8 + 4 + r];
    float fwd = g_fwd[(size_t)br*NN + t];
    g_rw[(size_t)br*NN + t] = cm*rc + fm*fwd + bm*bwd;
}

// ------------------- kernel 6: split-N GEMV partials ------------------------
__global__ void __launch_bounds__(256) k_gemv() {
    __shared__ float s_rw[RR*128];
    __shared__ float s_acc[4*RR*WW];
    int b  = blockIdx.x >> 3;
    int ch = blockIdx.x & 7;
    int t  = threadIdx.x;
    #pragma unroll
    for (int k = 0; k < 2; k++) {
        int q = k*256 + t;
        int r = q >> 7, n = q & 127;
        s_rw[r*128 + n] = g_rw[(size_t)(b*RR + r)*NN + ch*128 + n];
    }
    __syncthreads();
    int c = t & 63, sl = t >> 6;
    float a0=0.f, a1=0.f, a2=0.f, a3=0.f;
    #pragma unroll 4
    for (int nn = 0; nn < 32; nn++) {
        int n = sl*32 + nn;
        float mv = g_mem_new[((size_t)(b*NN + ch*128 + n))*WW + c];
        a0 += s_rw[0*128 + n]*mv;
        a1 += s_rw[1*128 + n]*mv;
        a2 += s_rw[2*128 + n]*mv;
        a3 += s_rw[3*128 + n]*mv;
    }
    s_acc[(sl*RR + 0)*WW + c] = a0;
    s_acc[(sl*RR + 1)*WW + c] = a1;
    s_acc[(sl*RR + 2)*WW + c] = a2;
    s_acc[(sl*RR + 3)*WW + c] = a3;
    __syncthreads();
    {
        int r = t >> 6, cc = t & 63;
        float s = 0.f;
        #pragma unroll
        for (int sl2 = 0; sl2 < 4; sl2++) s += s_acc[(sl2*RR + r)*WW + cc];
        g_outP[(size_t)ch*(BB*RR*WW) + (b*RR + r)*WW + cc] = s;
    }
}

// ------------------- kernel 7: combine GEMV partials -------------------------
__global__ void __launch_bounds__(256) k_fin(float* __restrict__ out) {
    int b = blockIdx.x, t = threadIdx.x;
    float s = 0.f;
    #pragma unroll
    for (int ch = 0; ch < 8; ch++)
        s += g_outP[(size_t)ch*(BB*RR*WW) + b*RR*WW + t];
    out[b*RR*WW + t] = s;
}

// ------------------- launch -------------------------------------------------
extern "C" void kernel_launch(void* const* d_in, const int* in_sizes, int n_in,
                              void* d_out, int out_size) {
    const float* memory   = (const float*)d_in[0];
    const float* usage_p  = (const float*)d_in[1];
    const float* link_p   = (const float*)d_in[2];
    const float* prec_p   = (const float*)d_in[3];
    const float* rwp      = (const float*)d_in[4];
    const float* wwp      = (const float*)d_in[5];
    const float* rkeys    = (const float*)d_in[6];
    const float* rstr     = (const float*)d_in[7];
    const float* wkeys    = (const float*)d_in[8];
    const float* wstr     = (const float*)d_in[9];
    const float* erase    = (const float*)d_in[10];
    const float* wvec     = (const float*)d_in[11];
    const float* fgate    = (const float*)d_in[12];
    const float* agate    = (const float*)d_in[13];
    const float* wgate    = (const float*)d_in[14];
    const float* rmode    = (const float*)d_in[15];
    float* out = (float*)d_out;

    static cudaStream_t s2 = nullptr, s3 = nullptr;
    static cudaEvent_t evFork0 = nullptr, evW = nullptr, evFork = nullptr, evJ3 = nullptr;
    if (s2 == nullptr) {
        cudaStreamCreateWithFlags(&s2, cudaStreamNonBlocking);
        cudaStreamCreateWithFlags(&s3, cudaStreamNonBlocking);
        cudaEventCreateWithFlags(&evFork0, cudaEventDisableTiming);
        cudaEventCreateWithFlags(&evW, cudaEventDisableTiming);
        cudaEventCreateWithFlags(&evFork, cudaEventDisableTiming);
        cudaEventCreateWithFlags(&evJ3, cudaEventDisableTiming);
    }

    cudaEventRecord(evFork0, 0);
    cudaStreamWaitEvent(s2, evFork0, 0);
    k_wdot<<<BB*8, 128, 0, s2>>>(memory, wkeys, wstr);
    cudaEventRecord(evW, s2);

    k_sort<<<BB, 1024>>>(usage_p, wwp, fgate, rwp);

    cudaStreamWaitEvent(0, evW, 0);
    k_alloc2<<<BB, 1024>>>(rwp, prec_p, agate, wgate);

    cudaEventRecord(evFork, 0);
    cudaStreamWaitEvent(s3, evFork, 0);
    k_memnew_rcdot<<<BB*8, 256, 0, s3>>>(memory, erase, wvec, rkeys, rstr);
    cudaEventRecord(evJ3, s3);

    k_link<<<BB*16, 256>>>(link_p);

    cudaStreamWaitEvent(0, evJ3, 0);
    k_rw<<<BB*RR, 1024>>>(prec_p, rmode);
    k_gemv<<<BB*8, 256>>>();
    k_fin<<<BB, 256>>>(out);
}

// round 13
// speedup vs baseline: 1.0675x; 1.0675x over previous
#include <cuda_runtime.h>
#include <cstdint>

#define BB 32
#define NN 1024
#define WW 64
#define RR 4
#define EPSF 1e-5f

// ------------------- device scratch (no allocations allowed) ----------------
__device__ float g_wc[BB*NN];                     // write sharp (pre-softmax)
__device__ float g_ww[BB*NN];
__device__ float g_mem_new[BB*NN*WW];
__device__ __align__(16) float2 g_uv[BB*NN*RR];   // (u, u*w) per (b,m,r)
__device__ float g_scal[BB*8];                    // c[0..3], d[0..3]
__device__ float g_fwd[BB*RR*NN];
__device__ float g_bwdP[32*BB*RR*NN];             // 32 slabs of col partials
__device__ float g_rc[BB*RR*NN];                  // read sharp (pre-softmax)
__device__ float g_rw[BB*RR*NN];                  // final read weights

// ------------------- helpers ------------------------------------------------
__device__ __forceinline__ unsigned long long pack2(float x, float y){
    unsigned long long r; asm("mov.b64 %0, {%1, %2};" : "=l"(r) : "f"(x), "f"(y)); return r;
}
__device__ __forceinline__ void unpack2(unsigned long long p, float &x, float &y){
    asm("mov.b64 {%0, %1}, %2;" : "=f"(x), "=f"(y) : "l"(p));
}
__device__ __forceinline__ void fma2(unsigned long long &d, unsigned long long a, unsigned long long b){
    asm("fma.rn.f32x2 %0, %1, %2, %0;" : "+l"(d) : "l"(a), "l"(b));
}
__device__ __forceinline__ float softplusf(float x){
    return fmaxf(x, 0.0f) + log1pf(expf(-fabsf(x)));
}

// ------------------- kernel 1: write-key dots (sharp) ------------------------
__global__ void __launch_bounds__(128) k_wdot(const float* __restrict__ memory,
                                              const float* __restrict__ wkeys,
                                              const float* __restrict__ wstr) {
    __shared__ float s_key[WW];
    __shared__ float s_kn, s_sp;
    int b = blockIdx.x >> 3;
    int n0 = (blockIdx.x & 7) * 128;
    int t = threadIdx.x;
    if (t < WW) s_key[t] = wkeys[b*WW + t];
    __syncthreads();
    if (t == 0) {
        float ss = 0.f;
        #pragma unroll
        for (int c = 0; c < WW; c++) ss += s_key[c]*s_key[c];
        s_kn = sqrtf(ss + EPSF);
        s_sp = softplusf(wstr[b]);
    }
    __syncthreads();
    int n = n0 + t;
    const float4* row = (const float4*)(memory + ((size_t)(b*NN + n))*WW);
    float dot = 0.f, sq = 0.f;
    #pragma unroll
    for (int j = 0; j < 16; j++) {
        float4 v = row[j];
        dot += v.x*s_key[4*j] + v.y*s_key[4*j+1] + v.z*s_key[4*j+2] + v.w*s_key[4*j+3];
        sq  += v.x*v.x + v.y*v.y + v.z*v.z + v.w*v.w;
    }
    float mn = sqrtf(sq + EPSF);
    g_wc[b*NN + n] = dot / (s_kn*mn + EPSF) * s_sp;
}

// ------------------- kernel 2: softmax(wc) + usage + alloc + ww + scalars ---
__global__ void __launch_bounds__(1024) k_alloc(const float* __restrict__ up,
                                                const float* __restrict__ wwp,
                                                const float* __restrict__ fg,
                                                const float* __restrict__ rwp,
                                                const float* __restrict__ p_prev,
                                                const float* __restrict__ ag_,
                                                const float* __restrict__ wg_) {
    __shared__ unsigned long long s_sk[NN];
    __shared__ float s_alloc[NN];
    __shared__ float s_red[33];
    __shared__ float s_wp[32];
    __shared__ float s_red8[32][8];
    int b = blockIdx.x, i = threadIdx.x;
    int lane = i & 31, wid = i >> 5;

    // ---- write-content softmax
    float sharp = g_wc[b*NN + i];
    float m = sharp;
    for (int off = 16; off; off >>= 1) m = fmaxf(m, __shfl_xor_sync(~0u, m, off));
    if (lane == 0) s_red[wid] = m;
    __syncthreads();
    if (wid == 0) {
        float mm = s_red[lane];
        for (int off = 16; off; off >>= 1) mm = fmaxf(mm, __shfl_xor_sync(~0u, mm, off));
        if (lane == 0) s_red[32] = mm;
    }
    __syncthreads();
    float e = expf(sharp - s_red[32]);
    float s = e;
    for (int off = 16; off; off >>= 1) s += __shfl_xor_sync(~0u, s, off);
    __syncthreads();
    if (lane == 0) s_red[wid] = s;
    __syncthreads();
    if (wid == 0) {
        float ss = s_red[lane];
        for (int off = 16; off; off >>= 1) ss += __shfl_xor_sync(~0u, ss, off);
        if (lane == 0) s_red[32] = ss;
    }
    __syncthreads();
    float wc = e / s_red[32];

    // ---- usage
    float u0 = up[b*NN + i];
    float w0 = wwp[b*NN + i];
    float usage = u0 + (1.f - u0)*w0;
    float phi = 1.f;
    float uu[RR];
    #pragma unroll
    for (int r = 0; r < RR; r++) {
        float rw = rwp[(b*RR + r)*NN + i];
        uu[r] = rw;
        phi *= (1.f - fg[b*RR + r]*rw);
    }
    usage *= phi;
    float nu = 1.f - usage;

    // ---- hybrid bitonic sort, descending (ties -> smaller index first)
    unsigned long long key =
        ((unsigned long long)__float_as_uint(nu) << 10) | (unsigned int)(NN - 1 - i);
    #pragma unroll
    for (int k = 2; k <= 32; k <<= 1) {
        bool up_ = ((i & k) == 0);
        #pragma unroll
        for (int j = k >> 1; j >= 1; j >>= 1) {
            unsigned long long other = __shfl_xor_sync(~0u, key, j);
            bool lower = ((i & j) == 0);
            bool keepMax = (up_ == lower);
            key = keepMax ? (key > other ? key : other) : (key < other ? key : other);
        }
    }
    s_sk[i] = key;
    __syncthreads();
    for (int k = 64; k <= NN; k <<= 1) {
        for (int j = k >> 1; j >= 32; j >>= 1) {
            int ixj = i ^ j;
            if (ixj > i) {
                unsigned long long a = s_sk[i], c = s_sk[ixj];
                bool desc = ((i & k) == 0);
                if (desc ? (a < c) : (a > c)) { s_sk[i] = c; s_sk[ixj] = a; }
            }
            __syncthreads();
        }
        key = s_sk[i];
        bool up_ = ((i & k) == 0);
        #pragma unroll
        for (int j = 16; j >= 1; j >>= 1) {
            unsigned long long other = __shfl_xor_sync(~0u, key, j);
            bool lower = ((i & j) == 0);
            bool keepMax = (up_ == lower);
            key = keepMax ? (key > other ? key : other) : (key < other ? key : other);
        }
        s_sk[i] = key;
        __syncthreads();
    }

    float snu = __uint_as_float((unsigned int)(key >> 10));
    int oidx = (NN - 1) - (int)(key & (NN - 1));
    float v = 1.f - snu;

    // ---- hierarchical product scan (exclusive)
    float p = v;
    #pragma unroll
    for (int off = 1; off < 32; off <<= 1) {
        float t2 = __shfl_up_sync(~0u, p, off);
        if (lane >= off) p *= t2;
    }
    if (lane == 31) s_wp[wid] = p;
    __syncthreads();
    if (wid == 0) {
        float q = s_wp[lane];
        #pragma unroll
        for (int off = 1; off < 32; off <<= 1) {
            float t2 = __shfl_up_sync(~0u, q, off);
            if (lane >= off) q *= t2;
        }
        s_wp[lane] = q;
    }
    __syncthreads();
    float warpPref = (wid == 0) ? 1.f : s_wp[wid - 1];
    float inclPrev = __shfl_up_sync(~0u, p, 1);
    float excl = (lane == 0) ? warpPref : warpPref * inclPrev;
    s_alloc[oidx] = snu * excl;
    __syncthreads();

    // ---- write weights + uv + scalars
    float alloc = s_alloc[i];
    float ag = ag_[b], wg = wg_[b];
    float ww = wg * (ag*alloc + (1.f - ag)*wc);
    g_ww[b*NN + i] = ww;

    float pp = p_prev[b*NN + i];
    float part[8];
    #pragma unroll
    for (int r = 0; r < RR; r++) {
        g_uv[(b*NN + i)*RR + r] = make_float2(uu[r], uu[r]*ww);
        part[r]     = uu[r]*pp;   // c[r]
        part[4 + r] = uu[r]*ww;   // d[r]
    }
    #pragma unroll
    for (int j = 0; j < 8; j++)
        for (int off = 16; off; off >>= 1) part[j] += __shfl_xor_sync(~0u, part[j], off);
    if (lane == 0)
        for (int j = 0; j < 8; j++) s_red8[wid][j] = part[j];
    __syncthreads();
    if (wid == 0 && lane < 8) {
        float sum = 0.f;
        #pragma unroll
        for (int w = 0; w < 32; w++) sum += s_red8[w][lane];
        g_scal[b*8 + lane] = sum;
    }
}

// ------------------- kernel 3: fused memory update + read-key dots ----------
__global__ void __launch_bounds__(256) k_memnew_rcdot(const float* __restrict__ memory,
                                                      const float* __restrict__ erase,
                                                      const float* __restrict__ wv,
                                                      const float* __restrict__ rkeys,
                                                      const float* __restrict__ rstr) {
    __shared__ float s_m[128*65];
    __shared__ float s_keys[RR][WW];
    __shared__ float s_kn[RR], s_sp[RR];
    __shared__ float s_e[WW], s_v[WW];
    __shared__ float s_ww[128];
    int b  = blockIdx.x >> 3;
    int n0 = (blockIdx.x & 7) * 128;
    int t  = threadIdx.x;

    if (t < 256) s_keys[t >> 6][t & 63] = rkeys[b*RR*WW + t];
    if (t < WW) { s_e[t] = erase[b*WW + t]; s_v[t] = wv[b*WW + t]; }
    if (t < 128) s_ww[t] = g_ww[b*NN + n0 + t];
    __syncthreads();
    if (t < RR) {
        float ss = 0.f;
        #pragma unroll
        for (int c = 0; c < WW; c++) ss += s_keys[t][c]*s_keys[t][c];
        s_kn[t] = sqrtf(ss + EPSF);
        s_sp[t] = softplusf(rstr[b*RR + t]);
    }

    #pragma unroll
    for (int it = 0; it < 8; it++) {
        int q = it*256 + t;
        int row = q >> 4, c4 = q & 15;
        size_t gi = (size_t)(b*NN + n0 + row)*16 + c4;
        float4 mm = ((const float4*)memory)[gi];
        float ww = s_ww[row];
        float4 o;
        o.x = mm.x*(1.f - ww*s_e[4*c4+0]) + ww*s_v[4*c4+0];
        o.y = mm.y*(1.f - ww*s_e[4*c4+1]) + ww*s_v[4*c4+1];
        o.z = mm.z*(1.f - ww*s_e[4*c4+2]) + ww*s_v[4*c4+2];
        o.w = mm.w*(1.f - ww*s_e[4*c4+3]) + ww*s_v[4*c4+3];
        ((float4*)g_mem_new)[gi] = o;
        float* d = s_m + row*65 + c4*4;
        d[0] = o.x; d[1] = o.y; d[2] = o.z; d[3] = o.w;
    }
    __syncthreads();

    if (t < 128) {
        const float* rw = s_m + t*65;
        float acc0 = 0.f, acc1 = 0.f, acc2 = 0.f, acc3 = 0.f, sq = 0.f;
        #pragma unroll 8
        for (int c = 0; c < WW; c++) {
            float mv = rw[c];
            sq   += mv*mv;
            acc0 += mv*s_keys[0][c];
            acc1 += mv*s_keys[1][c];
            acc2 += mv*s_keys[2][c];
            acc3 += mv*s_keys[3][c];
        }
        float mn = sqrtf(sq + EPSF);
        int n = n0 + t;
        g_rc[(b*RR + 0)*NN + n] = acc0 / (s_kn[0]*mn + EPSF) * s_sp[0];
        g_rc[(b*RR + 1)*NN + n] = acc1 / (s_kn[1]*mn + EPSF) * s_sp[1];
        g_rc[(b*RR + 2)*NN + n] = acc2 / (s_kn[2]*mn + EPSF) * s_sp[2];
        g_rc[(b*RR + 3)*NN + n] = acc3 / (s_kn[3]*mn + EPSF) * s_sp[3];
    }
}

// ------------------- kernel 4: fused link contraction v3 (best known) -------
__global__ void __launch_bounds__(256, 4) k_link(const float* __restrict__ L) {
    __shared__ float s_L[64*132];          // 33792 B (reused for fwd combine)
    __shared__ float2 s_uvr[64*4];
    __shared__ float2 s_uvc[128*4];
    int b = blockIdx.x >> 4;
    int rb = blockIdx.x & 15;
    int n0 = rb * 64;
    int t = threadIdx.x;
    int lane = t & 31, wid = t >> 5;

    if (t < 128) ((float4*)s_uvr)[t] = ((const float4*)g_uv)[(size_t)(b*NN + n0)*2 + t];

    unsigned long long f0[RR] = {0ull,0ull,0ull,0ull};
    unsigned long long f1[RR] = {0ull,0ull,0ull,0ull};

    int wq  = wid - 4;
    int h   = (wq >> 1) & 1;
    int ch2 = wq & 1;
    int c0  = ch2*64 + 2*lane;

    for (int s = 0; s < 8; s++) {
        __syncthreads();
        #pragma unroll
        for (int k = 0; k < 8; k++) {
            int q = k*256 + t;
            int r_ = q >> 5, c4 = q & 31;
            float4 v = ((const float4*)L)[(size_t)(b*NN + n0 + r_)*256 + s*32 + c4];
            *(float4*)(s_L + r_*132 + c4*4) = v;
        }
        ((float4*)s_uvc)[t] = ((const float4*)g_uv)[(size_t)(b*NN + s*128)*2 + t];
        __syncthreads();

        if (t < 128) {
            const ulonglong2* uvc = (const ulonglong2*)s_uvc;
            int qb = wid * 32;
            const float4* Lr0 = (const float4*)(s_L + lane*132 + qb);
            const float4* Lr1 = (const float4*)(s_L + (lane+32)*132 + qb);
            #pragma unroll
            for (int j = 0; j < 8; j++) {
                float4 a0 = Lr0[j];
                float4 a1 = Lr1[j];
                #pragma unroll
                for (int jj = 0; jj < 4; jj++) {
                    int m = qb + 4*j + jj;
                    ulonglong2 pA = uvc[2*m];
                    ulonglong2 pB = uvc[2*m+1];
                    float x0 = (jj==0)?a0.x:(jj==1)?a0.y:(jj==2)?a0.z:a0.w;
                    float x1 = (jj==0)?a1.x:(jj==1)?a1.y:(jj==2)?a1.z:a1.w;
                    unsigned long long L0 = pack2(x0,x0), L1 = pack2(x1,x1);
                    fma2(f0[0], L0, pA.x); fma2(f0[1], L0, pA.y);
                    fma2(f0[2], L0, pB.x); fma2(f0[3], L0, pB.y);
                    fma2(f1[0], L1, pA.x); fma2(f1[1], L1, pA.y);
                    fma2(f1[2], L1, pB.x); fma2(f1[3], L1, pB.y);
                }
            }
        } else {
            const ulonglong2* uvr2 = (const ulonglong2*)s_uvr;
            unsigned long long ba[RR] = {0ull,0ull,0ull,0ull};
            unsigned long long bb[RR] = {0ull,0ull,0ull,0ull};
            int m0 = h*32;
            #pragma unroll 8
            for (int mm = 0; mm < 32; mm++) {
                int m = m0 + mm;
                float2 Lv = *(const float2*)(s_L + m*132 + c0);
                ulonglong2 pA = uvr2[2*m];
                ulonglong2 pB = uvr2[2*m+1];
                unsigned long long Lx = pack2(Lv.x, Lv.x), Ly = pack2(Lv.y, Lv.y);
                fma2(ba[0], Lx, pA.x); fma2(ba[1], Lx, pA.y);
                fma2(ba[2], Lx, pB.x); fma2(ba[3], Lx, pB.y);
                fma2(bb[0], Ly, pA.x); fma2(bb[1], Ly, pA.y);
                fma2(bb[2], Ly, pB.x); fma2(bb[3], Ly, pB.y);
            }
            int gcol = s*128 + c0;
            float2 w2 = *(const float2*)(g_ww + b*NN + gcol);
            int slab = rb*2 + h;
            size_t base = (size_t)slab*(BB*RR*NN) + (size_t)(b*RR)*NN + gcol;
            #pragma unroll
            for (int r = 0; r < RR; r++) {
                float A0, B0, A1, B1;
                unpack2(ba[r], A0, B0);
                unpack2(bb[r], A1, B1);
                float2 outv;
                outv.x = (1.f - w2.x)*A0 - B0;
                outv.y = (1.f - w2.y)*A1 - B1;
                *(float2*)(g_bwdP + base + (size_t)r*NN) = outv;
            }
        }
    }

    __syncthreads();
    if (t < 128) {
        int w4 = wid;
        #pragma unroll
        for (int r = 0; r < RR; r++) {
            float A, Bv;
            unpack2(f0[r], A, Bv);
            s_L[lane*32 + w4*8 + 2*r]     = A;
            s_L[lane*32 + w4*8 + 2*r + 1] = Bv;
            unpack2(f1[r], A, Bv);
            s_L[(lane+32)*32 + w4*8 + 2*r]     = A;
            s_L[(lane+32)*32 + w4*8 + 2*r + 1] = Bv;
        }
    }
    __syncthreads();
    {
        int row = t >> 2, r = t & 3;
        float A = 0.f, Bv = 0.f;
        #pragma unroll
        for (int w4 = 0; w4 < 4; w4++) {
            A  += s_L[row*32 + w4*8 + 2*r];
            Bv += s_L[row*32 + w4*8 + 2*r + 1];
        }
        int n = n0 + row;
        float wn = g_ww[b*NN + n];
        g_fwd[(size_t)(b*RR + r)*NN + n] = (1.f - wn)*A - Bv + wn*g_scal[b*8 + r];
    }
}

// ------------------- kernel 5: read softmax + read weights + zero out -------
__global__ void __launch_bounds__(1024) k_rw(const float* __restrict__ p_prev,
                                             const float* __restrict__ rmode,
                                             float* __restrict__ out) {
    __shared__ float s_red[33];
    int br = blockIdx.x;               // b*RR + r
    int b = br >> 2, r = br & 3;
    int t = threadIdx.x, lane = t & 31, wid = t >> 5;

    // zero this block's 64 output slots (k_gemv atomically accumulates)
    if (t < WW) out[br*WW + t] = 0.f;

    const float* rm = rmode + br*3;
    float v0 = rm[0], v1 = rm[1], v2 = rm[2];
    float mx3 = fmaxf(v0, fmaxf(v1, v2));
    float e0 = expf(v0 - mx3), e1 = expf(v1 - mx3), e2 = expf(v2 - mx3);
    float inv3 = 1.f / (e0 + e1 + e2);
    float bm = e0*inv3, fm = e1*inv3, cm = e2*inv3;

    float sharp = g_rc[br*NN + t];
    float m = sharp;
    for (int off = 16; off; off >>= 1) m = fmaxf(m, __shfl_xor_sync(~0u, m, off));
    if (lane == 0) s_red[wid] = m;
    __syncthreads();
    if (wid == 0) {
        float mm = s_red[lane];
        for (int off = 16; off; off >>= 1) mm = fmaxf(mm, __shfl_xor_sync(~0u, mm, off));
        if (lane == 0) s_red[32] = mm;
    }
    __syncthreads();
    float e = expf(sharp - s_red[32]);
    float s = e;
    for (int off = 16; off; off >>= 1) s += __shfl_xor_sync(~0u, s, off);
    __syncthreads();
    if (lane == 0) s_red[wid] = s;
    __syncthreads();
    if (wid == 0) {
        float ss = s_red[lane];
        for (int off = 16; off; off >>= 1) ss += __shfl_xor_sync(~0u, ss, off);
        if (lane == 0) s_red[32] = ss;
    }
    __syncthreads();
    float rc = e / s_red[32];

    float bsum = 0.f;
    #pragma unroll
    for (int sl = 0; sl < 32; sl++)
        bsum += g_bwdP[(size_t)sl*(BB*RR*NN) + (size_t)br*NN + t];
    float bwd = bsum + p_prev[b*NN + t]*g_scal[b*8 + 4 + r];
    float fwd = g_fwd[(size_t)br*NN + t];
    g_rw[(size_t)br*NN + t] = cm*rc + fm*fwd + bm*bwd;
}

// ------------------- kernel 6: split-N GEMV, atomic accumulate into out ------
__global__ void __launch_bounds__(256) k_gemv(float* __restrict__ out) {
    __shared__ float s_rw[RR*128];
    __shared__ float s_acc[4*RR*WW];
    int b  = blockIdx.x >> 3;
    int ch = blockIdx.x & 7;
    int t  = threadIdx.x;
    #pragma unroll
    for (int k = 0; k < 2; k++) {
        int q = k*256 + t;
        int r = q >> 7, n = q & 127;
        s_rw[r*128 + n] = g_rw[(size_t)(b*RR + r)*NN + ch*128 + n];
    }
    __syncthreads();
    int c = t & 63, sl = t >> 6;
    float a0=0.f, a1=0.f, a2=0.f, a3=0.f;
    #pragma unroll 4
    for (int nn = 0; nn < 32; nn++) {
        int n = sl*32 + nn;
        float mv = g_mem_new[((size_t)(b*NN + ch*128 + n))*WW + c];
        a0 += s_rw[0*128 + n]*mv;
        a1 += s_rw[1*128 + n]*mv;
        a2 += s_rw[2*128 + n]*mv;
        a3 += s_rw[3*128 + n]*mv;
    }
    s_acc[(sl*RR + 0)*WW + c] = a0;
    s_acc[(sl*RR + 1)*WW + c] = a1;
    s_acc[(sl*RR + 2)*WW + c] = a2;
    s_acc[(sl*RR + 3)*WW + c] = a3;
    __syncthreads();
    {
        int r = t >> 6, cc = t & 63;
        float s = 0.f;
        #pragma unroll
        for (int sl2 = 0; sl2 < 4; sl2++) s += s_acc[(sl2*RR + r)*WW + cc];
        atomicAdd(&out[(b*RR + r)*WW + cc], s);
    }
}

// ------------------- launch -------------------------------------------------
extern "C" void kernel_launch(void* const* d_in, const int* in_sizes, int n_in,
                              void* d_out, int out_size) {
    const float* memory   = (const float*)d_in[0];
    const float* usage_p  = (const float*)d_in[1];
    const float* link_p   = (const float*)d_in[2];
    const float* prec_p   = (const float*)d_in[3];
    const float* rwp      = (const float*)d_in[4];
    const float* wwp      = (const float*)d_in[5];
    const float* rkeys    = (const float*)d_in[6];
    const float* rstr     = (const float*)d_in[7];
    const float* wkeys    = (const float*)d_in[8];
    const float* wstr     = (const float*)d_in[9];
    const float* erase    = (const float*)d_in[10];
    const float* wvec     = (const float*)d_in[11];
    const float* fgate    = (const float*)d_in[12];
    const float* agate    = (const float*)d_in[13];
    const float* wgate    = (const float*)d_in[14];
    const float* rmode    = (const float*)d_in[15];
    float* out = (float*)d_out;

    static cudaStream_t s3 = nullptr;
    static cudaEvent_t evFork = nullptr, evJ3 = nullptr;
    if (s3 == nullptr) {
        cudaStreamCreateWithFlags(&s3, cudaStreamNonBlocking);
        cudaEventCreateWithFlags(&evFork, cudaEventDisableTiming);
        cudaEventCreateWithFlags(&evJ3, cudaEventDisableTiming);
    }

    k_wdot<<<BB*8, 128>>>(memory, wkeys, wstr);
    k_alloc<<<BB, 1024>>>(usage_p, wwp, fgate, rwp, prec_p, agate, wgate);

    // fork: memnew_rcdot (s3) concurrent with k_link (stream 0)
    cudaEventRecord(evFork, 0);
    cudaStreamWaitEvent(s3, evFork, 0);
    k_memnew_rcdot<<<BB*8, 256, 0, s3>>>(memory, erase, wvec, rkeys, rstr);
    cudaEventRecord(evJ3, s3);

    k_link<<<BB*16, 256>>>(link_p);

    cudaStreamWaitEvent(0, evJ3, 0);
    k_rw<<<BB*RR, 1024>>>(prec_p, rmode, out);
    k_gemv<<<BB*8, 256>>>(out);
}